// round 15
// baseline (speedup 1.0000x reference)
#include <cuda_runtime.h>
#include <cuda_fp16.h>
#include <cstdint>

#define CIN   256
#define COUT  256
#define HWD   64
#define NB    32
#define NPIX  4096
#define KTOT  2304            // 9 * 256
#define NSTAGE 36             // K chunks of 64

#define XROW  144             // padded row bytes for x tile [px128][k64] fp16
#define WROW  144             // padded row bytes for w tile [co][k64] fp16
#define X_SZ  (128 * XROW)    // 18432
#define W_SZ  (256 * WROW)    // 36864
#define ST_SZ (X_SZ + W_SZ)   // 55296
#define NRING 3
#define SMEM_BYTES (NRING * ST_SZ)   // 165888

#define NTBLK 2048            // x-transpose blocks in k_pre

// ---------------- device scratch ---------------------------------------------
__device__ __half g_wh[(size_t)NB * COUT * KTOT];          // modulated w fp16, K-major
__device__ __half g_xn[(size_t)NB * NPIX * CIN];           // x fp16, NHWC [b][px][ci]

// ---------------- helpers -----------------------------------------------------
__device__ __forceinline__ uint32_t smem_u32(const void* p) {
    uint32_t a;
    asm("{ .reg .u64 t; cvta.to.shared.u64 t, %1; cvt.u32.u64 %0, t; }" : "=r"(a) : "l"(p));
    return a;
}
__device__ __forceinline__ void cp16(uint32_t dst, const void* src) {
    asm volatile("cp.async.cg.shared.global [%0], [%1], 16;" :: "r"(dst), "l"(src));
}
__device__ __forceinline__ void cp16z(uint32_t dst, const void* src, uint32_t nbytes) {
    asm volatile("cp.async.cg.shared.global [%0], [%1], 16, %2;"
                 :: "r"(dst), "l"(src), "r"(nbytes));
}
__device__ __forceinline__ void cp_commit() { asm volatile("cp.async.commit_group;"); }
__device__ __forceinline__ void cp_wait1()  { asm volatile("cp.async.wait_group 1;"); }

__device__ __forceinline__ void ldsm4(uint32_t* r, uint32_t a) {
    asm volatile("ldmatrix.sync.aligned.m8n8.x4.shared.b16 {%0,%1,%2,%3}, [%4];"
                 : "=r"(r[0]), "=r"(r[1]), "=r"(r[2]), "=r"(r[3]) : "r"(a));
}
__device__ __forceinline__ void mma16816(float* c, const uint32_t* a, const uint32_t* b) {
    asm volatile("mma.sync.aligned.m16n8k16.row.col.f32.f16.f16.f32 "
                 "{%0,%1,%2,%3}, {%4,%5,%6,%7}, {%8,%9}, {%0,%1,%2,%3};"
                 : "+f"(c[0]), "+f"(c[1]), "+f"(c[2]), "+f"(c[3])
                 : "r"(a[0]), "r"(a[1]), "r"(a[2]), "r"(a[3]), "r"(b[0]), "r"(b[1]));
}

// ---------------- single prologue kernel --------------------------------------
// blocks [0, NTBLK):     x NCHW fp32 -> NHWC fp16 transpose (64px x 256ci tiles)
// blocks [NTBLK, +8192): per-(b,co) wsq + demod + modulate + fp16, K-major
__global__ void k_pre(const float* __restrict__ x, const float* __restrict__ w,
                      const float* __restrict__ y) {
    if (blockIdx.x < NTBLK) {
        __shared__ __half xs[64 * 264];
        const int b  = blockIdx.x >> 6;
        const int p0 = (blockIdx.x & 63) * 64;
        const int t  = threadIdx.x;                        // t = ci
        const float* src = x + ((size_t)(b * CIN + t)) * NPIX + p0;
#pragma unroll
        for (int j = 0; j < 16; j++) {
            float4 v = *(const float4*)(src + j * 4);
            xs[(j * 4 + 0) * 264 + t] = __float2half_rn(v.x);
            xs[(j * 4 + 1) * 264 + t] = __float2half_rn(v.y);
            xs[(j * 4 + 2) * 264 + t] = __float2half_rn(v.z);
            xs[(j * 4 + 3) * 264 + t] = __float2half_rn(v.w);
        }
        __syncthreads();
        const int px = t & 63, q = t >> 6;                 // q = ci quarter
        __half* dst = g_xn + (((size_t)b * NPIX + p0 + px) << 8) + q * 64;
        const __half* srow = xs + px * 264 + q * 64;
#pragma unroll
        for (int u = 0; u < 8; u++)
            *(uint4*)(dst + u * 8) = *(const uint4*)(srow + u * 8);
    } else {
        // ---- self-contained w modulate: block = one (b, co) pair -------------
        __shared__ float ws[KTOT];
        __shared__ float sr[8];
        const int bc = blockIdx.x - NTBLK;
        const int co = bc & 255, b = bc >> 8;
        const int t  = threadIdx.x;                        // t = ci
        const float* wc = w + (size_t)co * KTOT;
#pragma unroll
        for (int i = 0; i < 9; i++) ws[t + i * 256] = wc[t + i * 256];
        __syncthreads();
        const float ym = y[b * CIN + t] + 1.0f;
        float s = 0.f;
#pragma unroll
        for (int k = 0; k < 9; k++) { float v = ws[t * 9 + k]; s += v * v; }
        float v = s * ym * ym;
#pragma unroll
        for (int o = 16; o; o >>= 1) v += __shfl_xor_sync(0xffffffffu, v, o);
        if ((t & 31) == 0) sr[t >> 5] = v;
        __syncthreads();
        const float d = rsqrtf(sr[0] + sr[1] + sr[2] + sr[3]
                               + sr[4] + sr[5] + sr[6] + sr[7] + 1e-8f);
        const float yd = ym * d;
        __half* wh = g_wh + (size_t)bc * KTOT;
#pragma unroll
        for (int kp = 0; kp < 9; kp++)
            wh[kp * 256 + t] = __float2half_rn(ws[t * 9 + kp] * yd);
    }
}

// ---------------- main conv: HMMA fp16 implicit GEMM, K64 stages --------------
// CTA: 128 pixels (M) x 256 cout (N), K = 2304, ring-3 cp.async, frag dbl-buf.
// A = x NHWC row-major [px][k]; shifts are whole-row gathers (always aligned).
__global__ void __launch_bounds__(256, 1) k_conv(const float* __restrict__ bias,
                                                 float* __restrict__ out) {
    extern __shared__ char smem[];
    const uint32_t sb0 = smem_u32(smem);
    const int t  = threadIdx.x;
    const int ln = t & 31;
    const int wp = t >> 5;
    const int wm = wp & 1;          // pixel half (64)
    const int wn = wp >> 1;         // cout quarter (64)
    const int b  = blockIdx.y;
    const int n0 = blockIdx.x * 128;
    const int r0 = blockIdx.x * 2;  // first image row of this tile

    const __half* gwh = g_wh + (size_t)b * COUT * KTOT;
    const __half* gxb = g_xn + ((size_t)b * NPIX << 8);

    // A: [px][k] row-major, ldsm4 non-trans; lane -> (pixel row, k 16B half)
    const uint32_t a_lane = (uint32_t)((wm * 64 + (ln & 7) + ((ln >> 3) & 1) * 8) * XROW
                                       + ((ln >> 4) & 1) * 16);
    const uint32_t b_lane = (uint32_t)(((ln & 7) + ((ln >> 4) & 1) * 8) * WROW
                                       + ((ln >> 3) & 1) * 16);

    float acc[4][8][4];
#pragma unroll
    for (int i = 0; i < 4; i++)
#pragma unroll
        for (int j = 0; j < 8; j++)
#pragma unroll
            for (int k = 0; k < 4; k++) acc[i][j][k] = 0.f;

    uint32_t Af[2][16], Bf[2][16];

    // ---- stage loader: X (4 chunks/thread) + W (8 chunks/thread) -------------
    auto load_stage = [&](int cs) {
        const int kp  = cs >> 2;                 // 0..8
        const int cic = (cs & 3) * 64;
        const int dr  = kp / 3 - 1;
        const int dc  = kp % 3 - 1;
        const uint32_t sbase = sb0 + (cs % NRING) * ST_SZ;
#pragma unroll
        for (int j = 0; j < 4; j++) {
            const int chunk = j * 256 + t;       // 0..1023
            const int px = chunk >> 3;           // 0..127 tile pixel
            const int g  = chunk & 7;            // 16B k-group
            const int gr = r0 + (px >> 6) + dr;
            const int gc = (px & 63) + dc;
            const bool ok = ((unsigned)gr < HWD) && ((unsigned)gc < HWD);
            const int grc = ok ? (gr * HWD + gc) : 0;
            const __half* src = gxb + (((size_t)grc) << 8) + cic + g * 8;
            cp16z(sbase + px * XROW + g * 16, src, ok ? 16u : 0u);
        }
        const __half* wbase = gwh + kp * 256 + cic;
        const uint32_t wdst = sbase + X_SZ;
#pragma unroll
        for (int q = 0; q < 8; q++) {
            const int chunk = q * 256 + t;       // 0..2047
            const int row = chunk >> 3;
            const int u   = chunk & 7;
            cp16(wdst + row * WROW + u * 16, wbase + (size_t)row * KTOT + u * 8);
        }
    };

    // ---- frag loader for k16 slice sl of the stage at (xs, ws) ---------------
    auto load_frags = [&](uint32_t xs, uint32_t ws, int sl, int pb) {
        const uint32_t ax = xs + a_lane + sl * 32;
#pragma unroll
        for (int mt = 0; mt < 4; mt++) ldsm4(&Af[pb][mt * 4], ax + mt * 16 * XROW);
        const uint32_t bw = ws + b_lane + wn * 64 * WROW + sl * 32;
        ldsm4(&Bf[pb][0],  bw);
        ldsm4(&Bf[pb][4],  bw + 16 * WROW);
        ldsm4(&Bf[pb][8],  bw + 32 * WROW);
        ldsm4(&Bf[pb][12], bw + 48 * WROW);
    };
    auto compute = [&](int pb) {
#pragma unroll
        for (int h = 0; h < 2; h++)
#pragma unroll
            for (int mt = 0; mt < 4; mt++)
#pragma unroll
                for (int q = 0; q < 4; q++)
                    mma16816(acc[mt][h * 4 + q], &Af[pb][mt * 4], &Bf[pb][h * 8 + q * 2]);
    };

    // ---- prime ----
    load_stage(0); cp_commit();
    load_stage(1); cp_commit();
    cp_wait1();
    __syncthreads();
    load_frags(sb0, sb0 + X_SZ, 0, 0);

#pragma unroll 1
    for (int c = 0; c < NSTAGE; c++) {
        const uint32_t xs = sb0 + (c % NRING) * ST_SZ;
        const uint32_t ws = xs + X_SZ;
        if (c + 2 < NSTAGE) load_stage(c + 2);
        cp_commit();

#pragma unroll
        for (int sl = 0; sl < 4; sl++) {
            const int pb = sl & 1;
            if (sl < 3) load_frags(xs, ws, sl + 1, pb ^ 1);
            compute(pb);
        }

        cp_wait1();
        __syncthreads();
        if (c + 1 < NSTAGE) {
            const uint32_t nxs = sb0 + ((c + 1) % NRING) * ST_SZ;
            load_frags(nxs, nxs + X_SZ, 0, 0);
        }
    }

    // ---- epilogue ----
#pragma unroll
    for (int h = 0; h < 2; h++)
#pragma unroll
        for (int q = 0; q < 4; q++) {
            const int co0 = wn * 64 + h * 32 + (q >> 1) * 16 + (q & 1) * 8 + (ln & 3) * 2;
            const float b0 = __ldg(&bias[co0]);
            const float b1 = __ldg(&bias[co0 + 1]);
#pragma unroll
            for (int mt = 0; mt < 4; mt++) {
                const int pix = n0 + wm * 64 + mt * 16 + (ln >> 2);
                float* o = out + ((size_t)b * COUT + co0) * NPIX + pix;
                const float* C = acc[mt][h * 4 + q];
                o[0]        = C[0] + b0;
                o[NPIX]     = C[1] + b1;
                o[8]        = C[2] + b0;
                o[NPIX + 8] = C[3] + b1;
            }
        }
}

// ---------------- launch ------------------------------------------------------
extern "C" void kernel_launch(void* const* d_in, const int* in_sizes, int n_in,
                              void* d_out, int out_size) {
    const float* x    = (const float*)d_in[0];
    const float* y    = (const float*)d_in[1];
    const float* w    = (const float*)d_in[2];
    const float* bias = (const float*)d_in[3];
    float* out        = (float*)d_out;

    cudaFuncSetAttribute(k_conv, cudaFuncAttributeMaxDynamicSharedMemorySize, SMEM_BYTES);

    k_pre<<<NTBLK + NB * COUT, 256>>>(x, w, y);
    k_conv<<<dim3(NPIX / 128, NB), 256, SMEM_BYTES>>>(bias, out);
}

// round 17
// speedup vs baseline: 1.1127x; 1.1127x over previous
#include <cuda_runtime.h>
#include <cuda_fp16.h>
#include <cstdint>

#define CIN   256
#define COUT  256
#define HWD   64
#define NB    32
#define NPIX  4096
#define KTOT  2304            // 9 * 256
#define NSTAGE 36             // K chunks of 64

#define XROW  144             // padded row bytes for x tile [px128][k64] fp16
#define WROW  144             // padded row bytes for w tile [co][k64] fp16
#define X_SZ  (128 * XROW)    // 18432
#define W_SZ  (256 * WROW)    // 36864
#define ST_SZ (X_SZ + W_SZ)   // 55296
#define NRING 3
#define SMEM_BYTES (NRING * ST_SZ)   // 165888

#define NTBLK 4096            // transpose blocks: 32 b x 8 ci-tiles x 16 px-tiles

// ---------------- device scratch ---------------------------------------------
__device__ __half g_wh[(size_t)NB * COUT * KTOT];          // modulated w fp16, K-major
__device__ __half g_xn[(size_t)NB * NPIX * CIN];           // x fp16, NHWC [b][px][ci]

// ---------------- helpers -----------------------------------------------------
__device__ __forceinline__ uint32_t smem_u32(const void* p) {
    uint32_t a;
    asm("{ .reg .u64 t; cvta.to.shared.u64 t, %1; cvt.u32.u64 %0, t; }" : "=r"(a) : "l"(p));
    return a;
}
__device__ __forceinline__ void cp16(uint32_t dst, const void* src) {
    asm volatile("cp.async.cg.shared.global [%0], [%1], 16;" :: "r"(dst), "l"(src));
}
__device__ __forceinline__ void cp16z(uint32_t dst, const void* src, uint32_t nbytes) {
    asm volatile("cp.async.cg.shared.global [%0], [%1], 16, %2;"
                 :: "r"(dst), "l"(src), "r"(nbytes));
}
__device__ __forceinline__ void cp_commit() { asm volatile("cp.async.commit_group;"); }
__device__ __forceinline__ void cp_wait1()  { asm volatile("cp.async.wait_group 1;"); }

__device__ __forceinline__ void ldsm4(uint32_t* r, uint32_t a) {
    asm volatile("ldmatrix.sync.aligned.m8n8.x4.shared.b16 {%0,%1,%2,%3}, [%4];"
                 : "=r"(r[0]), "=r"(r[1]), "=r"(r[2]), "=r"(r[3]) : "r"(a));
}
__device__ __forceinline__ void mma16816(float* c, const uint32_t* a, const uint32_t* b) {
    asm volatile("mma.sync.aligned.m16n8k16.row.col.f32.f16.f16.f32 "
                 "{%0,%1,%2,%3}, {%4,%5,%6,%7}, {%8,%9}, {%0,%1,%2,%3};"
                 : "+f"(c[0]), "+f"(c[1]), "+f"(c[2]), "+f"(c[3])
                 : "r"(a[0]), "r"(a[1]), "r"(a[2]), "r"(a[3]), "r"(b[0]), "r"(b[1]));
}

// ---------------- single prologue kernel --------------------------------------
// blocks [0, NTBLK):     tiled NCHW fp32 -> NHWC fp16 transpose (32ci x 256px)
// blocks [NTBLK, +8192): per-(b,co) wsq + demod + modulate + fp16, K-major
__global__ void k_pre(const float* __restrict__ x, const float* __restrict__ w,
                      const float* __restrict__ y) {
    if (blockIdx.x < NTBLK) {
        __shared__ __half xs[256 * 34];
        const int id  = blockIdx.x;
        const int pt  = id & 15;           // px tile
        const int cit = (id >> 4) & 7;     // ci tile
        const int b   = id >> 7;
        const int p0  = pt * 256;
        const int ci0 = cit * 32;
        const int t   = threadIdx.x;       // t = pixel within tile

        // read: 32 coalesced rows (one ci each), convert, smem [px][ci]
        const float* src = x + ((size_t)(b * CIN + ci0)) * NPIX + p0 + t;
#pragma unroll
        for (int i = 0; i < 32; i++)
            xs[t * 34 + i] = __float2half_rn(src[(size_t)i * NPIX]);
        __syncthreads();

        // write: 64B contiguous per pixel row; smem read via aligned 4B words
        __half* dst = g_xn + (((size_t)b * NPIX + p0 + t) << 8) + ci0;
        const uint32_t* srow = (const uint32_t*)xs + t * 17;   // 34 halves = 17 words
#pragma unroll
        for (int u = 0; u < 4; u++) {
            uint4 v;
            v.x = srow[u * 4 + 0];
            v.y = srow[u * 4 + 1];
            v.z = srow[u * 4 + 2];
            v.w = srow[u * 4 + 3];
            *(uint4*)(dst + u * 8) = v;
        }
    } else {
        // ---- self-contained w modulate: block = one (b, co) pair -------------
        __shared__ float ws[KTOT];
        __shared__ float sr[8];
        const int bc = blockIdx.x - NTBLK;
        const int co = bc & 255, b = bc >> 8;
        const int t  = threadIdx.x;                        // t = ci
        const float* wc = w + (size_t)co * KTOT;
#pragma unroll
        for (int i = 0; i < 9; i++) ws[t + i * 256] = wc[t + i * 256];
        __syncthreads();
        const float ym = y[b * CIN + t] + 1.0f;
        float s = 0.f;
#pragma unroll
        for (int k = 0; k < 9; k++) { float v = ws[t * 9 + k]; s += v * v; }
        float v = s * ym * ym;
#pragma unroll
        for (int o = 16; o; o >>= 1) v += __shfl_xor_sync(0xffffffffu, v, o);
        if ((t & 31) == 0) sr[t >> 5] = v;
        __syncthreads();
        const float d = rsqrtf(sr[0] + sr[1] + sr[2] + sr[3]
                               + sr[4] + sr[5] + sr[6] + sr[7] + 1e-8f);
        const float yd = ym * d;
        __half* wh = g_wh + (size_t)bc * KTOT;
#pragma unroll
        for (int kp = 0; kp < 9; kp++)
            wh[kp * 256 + t] = __float2half_rn(ws[t * 9 + kp] * yd);
    }
}

// ---------------- main conv: HMMA fp16 implicit GEMM, K64 stages --------------
// CTA: 128 pixels (M) x 256 cout (N), K = 2304, ring-3 cp.async, frag dbl-buf.
// A = x NHWC row-major [px][k]; shifts are whole-row gathers (always aligned).
__global__ void __launch_bounds__(256, 1) k_conv(const float* __restrict__ bias,
                                                 float* __restrict__ out) {
    extern __shared__ char smem[];
    const uint32_t sb0 = smem_u32(smem);
    const int t  = threadIdx.x;
    const int ln = t & 31;
    const int wp = t >> 5;
    const int wm = wp & 1;          // pixel half (64)
    const int wn = wp >> 1;         // cout quarter (64)
    const int b  = blockIdx.y;
    const int n0 = blockIdx.x * 128;
    const int r0 = blockIdx.x * 2;  // first image row of this tile

    const __half* gwh = g_wh + (size_t)b * COUT * KTOT;
    const __half* gxb = g_xn + ((size_t)b * NPIX << 8);

    // A: [px][k] row-major, ldsm4 non-trans; lane -> (pixel row, k 16B half)
    const uint32_t a_lane = (uint32_t)((wm * 64 + (ln & 7) + ((ln >> 3) & 1) * 8) * XROW
                                       + ((ln >> 4) & 1) * 16);
    const uint32_t b_lane = (uint32_t)(((ln & 7) + ((ln >> 4) & 1) * 8) * WROW
                                       + ((ln >> 3) & 1) * 16);

    float acc[4][8][4];
#pragma unroll
    for (int i = 0; i < 4; i++)
#pragma unroll
        for (int j = 0; j < 8; j++)
#pragma unroll
            for (int k = 0; k < 4; k++) acc[i][j][k] = 0.f;

    uint32_t Af[2][16], Bf[2][16];

    // ---- stage loader: X (4 chunks/thread) + W (8 chunks/thread) -------------
    auto load_stage = [&](int cs) {
        const int kp  = cs >> 2;                 // 0..8
        const int cic = (cs & 3) * 64;
        const int dr  = kp / 3 - 1;
        const int dc  = kp % 3 - 1;
        const uint32_t sbase = sb0 + (cs % NRING) * ST_SZ;
#pragma unroll
        for (int j = 0; j < 4; j++) {
            const int chunk = j * 256 + t;       // 0..1023
            const int px = chunk >> 3;           // 0..127 tile pixel
            const int g  = chunk & 7;            // 16B k-group
            const int gr = r0 + (px >> 6) + dr;
            const int gc = (px & 63) + dc;
            const bool ok = ((unsigned)gr < HWD) && ((unsigned)gc < HWD);
            const int grc = ok ? (gr * HWD + gc) : 0;
            const __half* src = gxb + (((size_t)grc) << 8) + cic + g * 8;
            cp16z(sbase + px * XROW + g * 16, src, ok ? 16u : 0u);
        }
        const __half* wbase = gwh + kp * 256 + cic;
        const uint32_t wdst = sbase + X_SZ;
#pragma unroll
        for (int q = 0; q < 8; q++) {
            const int chunk = q * 256 + t;       // 0..2047
            const int row = chunk >> 3;
            const int u   = chunk & 7;
            cp16(wdst + row * WROW + u * 16, wbase + (size_t)row * KTOT + u * 8);
        }
    };

    // ---- frag loader for k16 slice sl of the stage at (xs, ws) ---------------
    auto load_frags = [&](uint32_t xs, uint32_t ws, int sl, int pb) {
        const uint32_t ax = xs + a_lane + sl * 32;
#pragma unroll
        for (int mt = 0; mt < 4; mt++) ldsm4(&Af[pb][mt * 4], ax + mt * 16 * XROW);
        const uint32_t bw = ws + b_lane + wn * 64 * WROW + sl * 32;
        ldsm4(&Bf[pb][0],  bw);
        ldsm4(&Bf[pb][4],  bw + 16 * WROW);
        ldsm4(&Bf[pb][8],  bw + 32 * WROW);
        ldsm4(&Bf[pb][12], bw + 48 * WROW);
    };
    auto compute = [&](int pb) {
#pragma unroll
        for (int h = 0; h < 2; h++)
#pragma unroll
            for (int mt = 0; mt < 4; mt++)
#pragma unroll
                for (int q = 0; q < 4; q++)
                    mma16816(acc[mt][h * 4 + q], &Af[pb][mt * 4], &Bf[pb][h * 8 + q * 2]);
    };

    // ---- prime ----
    load_stage(0); cp_commit();
    load_stage(1); cp_commit();
    cp_wait1();
    __syncthreads();
    load_frags(sb0, sb0 + X_SZ, 0, 0);

#pragma unroll 1
    for (int c = 0; c < NSTAGE; c++) {
        const uint32_t xs = sb0 + (c % NRING) * ST_SZ;
        const uint32_t ws = xs + X_SZ;
        if (c + 2 < NSTAGE) load_stage(c + 2);
        cp_commit();

#pragma unroll
        for (int sl = 0; sl < 4; sl++) {
            const int pb = sl & 1;
            if (sl < 3) load_frags(xs, ws, sl + 1, pb ^ 1);
            compute(pb);
        }

        cp_wait1();
        __syncthreads();
        if (c + 1 < NSTAGE) {
            const uint32_t nxs = sb0 + ((c + 1) % NRING) * ST_SZ;
            load_frags(nxs, nxs + X_SZ, 0, 0);
        }
    }

    // ---- epilogue ----
#pragma unroll
    for (int h = 0; h < 2; h++)
#pragma unroll
        for (int q = 0; q < 4; q++) {
            const int co0 = wn * 64 + h * 32 + (q >> 1) * 16 + (q & 1) * 8 + (ln & 3) * 2;
            const float b0 = __ldg(&bias[co0]);
            const float b1 = __ldg(&bias[co0 + 1]);
#pragma unroll
            for (int mt = 0; mt < 4; mt++) {
                const int pix = n0 + wm * 64 + mt * 16 + (ln >> 2);
                float* o = out + ((size_t)b * COUT + co0) * NPIX + pix;
                const float* C = acc[mt][h * 4 + q];
                o[0]        = C[0] + b0;
                o[NPIX]     = C[1] + b1;
                o[8]        = C[2] + b0;
                o[NPIX + 8] = C[3] + b1;
            }
        }
}

// ---------------- launch ------------------------------------------------------
extern "C" void kernel_launch(void* const* d_in, const int* in_sizes, int n_in,
                              void* d_out, int out_size) {
    const float* x    = (const float*)d_in[0];
    const float* y    = (const float*)d_in[1];
    const float* w    = (const float*)d_in[2];
    const float* bias = (const float*)d_in[3];
    float* out        = (float*)d_out;

    cudaFuncSetAttribute(k_conv, cudaFuncAttributeMaxDynamicSharedMemorySize, SMEM_BYTES);

    k_pre<<<NTBLK + NB * COUT, 256>>>(x, w, y);
    k_conv<<<dim3(NPIX / 128, NB), 256, SMEM_BYTES>>>(bias, out);
}